// round 1
// baseline (speedup 1.0000x reference)
#include <cuda_runtime.h>

// Problem constants
#define BB 4
#define TT 256
#define II 512
#define HH 8
#define VV 32000
#define DD 512
#define BT (BB * TT)
#define V4 (VV / 4)

// Scratch (allocation-free rule: __device__ globals)
__device__ float g_attn[BB * TT * II];   // mean over heads  (2 MB)
__device__ int   g_idx[BB * VV];         // vocab -> slot or -1 (512 KB)
__device__ int   g_sl[BB * II];          // input pos -> slot
__device__ int   g_K[BB];                // distinct tokens per batch
__device__ float g_P[BB * TT * II];      // compact scattered sums (2 MB)
__device__ float g_lse[BT];
__device__ float g_pg[BT];
__device__ float g_ew[BB * II];          // enc row . w[0:D]

// ---------------------------------------------------------------------------
// 1) attn = mean_h attn_heads  (vectorized float4)
// ---------------------------------------------------------------------------
__global__ void k_reduce_heads(const float4* __restrict__ heads) {
    int i = blockIdx.x * blockDim.x + threadIdx.x;
    const int per_b = TT * II / 4;
    if (i >= BB * per_b) return;
    int b = i / per_b;
    int r = i - b * per_b;
    const float4* p = heads + (long)b * HH * per_b + r;
    float4 s = make_float4(0.f, 0.f, 0.f, 0.f);
#pragma unroll
    for (int h = 0; h < HH; h++) {
        float4 v = p[(long)h * per_b];
        s.x += v.x; s.y += v.y; s.z += v.z; s.w += v.w;
    }
    const float inv = 1.0f / HH;
    s.x *= inv; s.y *= inv; s.z *= inv; s.w *= inv;
    reinterpret_cast<float4*>(g_attn)[i] = s;
}

// ---------------------------------------------------------------------------
// 2a) idx = -1
// ---------------------------------------------------------------------------
__global__ void k_init_idx() {
    int i = blockIdx.x * blockDim.x + threadIdx.x;
    if (i < BB * VV) g_idx[i] = -1;
}

// 2b) deterministic slot assignment (one thread per batch, sequential over I)
__global__ void k_slots(const int* __restrict__ tok) {
    int b = threadIdx.x;
    if (b >= BB) return;
    int k = 0;
    for (int i = 0; i < II; i++) {
        int t = tok[b * II + i];
        int cur = g_idx[b * VV + t];
        if (cur < 0) {
            g_idx[b * VV + t] = k;
            g_sl[b * II + i] = k;
            k++;
        } else {
            g_sl[b * II + i] = cur;
        }
    }
    g_K[b] = k;
}

// ---------------------------------------------------------------------------
// 2c) ew[b,i] = enc[b,i,:] . w[0:D]   (one warp per row)
// ---------------------------------------------------------------------------
__global__ void k_ew(const float* __restrict__ enc, const float* __restrict__ w) {
    int row  = blockIdx.x * (blockDim.x / 32) + (threadIdx.x >> 5);
    int lane = threadIdx.x & 31;
    if (row >= BB * II) return;
    const float* e = enc + (long)row * DD;
    float s = 0.f;
    for (int d = lane; d < DD; d += 32) s += e[d] * w[d];
#pragma unroll
    for (int o = 16; o; o >>= 1) s += __shfl_down_sync(0xffffffffu, s, o);
    if (lane == 0) g_ew[row] = s;
}

// ---------------------------------------------------------------------------
// 3) Per-(b,t): compact scatter histogram, logsumexp, p_gen
// ---------------------------------------------------------------------------
__global__ void k_bt(const float* __restrict__ dec, const float* __restrict__ tar,
                     const float* __restrict__ w, const float* __restrict__ wb,
                     float* __restrict__ out_pg) {
    __shared__ float acc[II];
    __shared__ float r0[8], r1[8];
    const int bt  = blockIdx.x;
    const int b   = bt / TT;
    const int tid = threadIdx.x;

    acc[tid]       = 0.f;
    acc[tid + 256] = 0.f;
    __syncthreads();

    const float* arow = g_attn + (long)bt * II;
    float dot = 0.f;
    for (int i = tid; i < II; i += 256) {
        float a = arow[i];
        atomicAdd(&acc[g_sl[b * II + i]], a);
        dot += a * g_ew[b * II + i];
    }
    const float* drow = dec + (long)bt * DD;
    const float* trow = tar + (long)bt * DD;
    for (int d = tid; d < DD; d += 256)
        dot += drow[d] * w[DD + d] + trow[d] * w[2 * DD + d];
    __syncthreads();

    const int K = g_K[b];
    float se = 0.f;
    for (int k = tid; k < K; k += 256) se += expf(acc[k]);

    // dual block reduce (dot, se)
#pragma unroll
    for (int o = 16; o; o >>= 1) {
        dot += __shfl_down_sync(0xffffffffu, dot, o);
        se  += __shfl_down_sync(0xffffffffu, se, o);
    }
    int wp = tid >> 5, ln = tid & 31;
    if (ln == 0) { r0[wp] = dot; r1[wp] = se; }
    __syncthreads();
    if (tid == 0) {
        float dtot = 0.f, stot = 0.f;
#pragma unroll
        for (int q = 0; q < 8; q++) { dtot += r0[q]; stot += r1[q]; }
        float lse = logf((float)(VV - K) + stot);
        g_lse[bt] = lse;
        float p = 1.f / (1.f + expf(-(dtot + wb[0])));
        g_pg[bt]   = p;
        out_pg[bt] = p;
    }
    __syncthreads();
    float* Prow = g_P + (long)bt * II;
    Prow[tid]       = acc[tid];
    Prow[tid + 256] = acc[tid + 256];
}

// ---------------------------------------------------------------------------
// 4) Streaming output: final + pointer  (the HBM-bound kernel)
// ---------------------------------------------------------------------------
__global__ void __launch_bounds__(256) k_out(
    const float4* __restrict__ gen,
    const float*  __restrict__ psw_p, const float* __restrict__ psb_p,
    float4* __restrict__ out_final, float4* __restrict__ out_ptr)
{
    long i = (long)blockIdx.x * blockDim.x + threadIdx.x;
    const long total = (long)BT * V4;
    if (i >= total) return;
    int bt = (int)(i / V4);
    int v4 = (int)(i - (long)bt * V4);
    int b  = bt / TT;

    float4 g = __ldg(gen + i);
    const int4* idx4 = reinterpret_cast<const int4*>(g_idx);
    int4 id = __ldg(idx4 + (long)b * V4 + v4);

    float l   = __ldg(g_lse + bt);
    float p   = __ldg(g_pg + bt);
    float psw = __ldg(psw_p);
    float psb = __ldg(psb_p);
    float q    = 1.f - p;
    float base = psb - psw * l;   // pointer = psw*s + base
    const float* Prow = g_P + (long)bt * II;

    float4 pt, f;
    pt.x = (id.x >= 0 ? psw * Prow[id.x] : 0.f) + base;
    pt.y = (id.y >= 0 ? psw * Prow[id.y] : 0.f) + base;
    pt.z = (id.z >= 0 ? psw * Prow[id.z] : 0.f) + base;
    pt.w = (id.w >= 0 ? psw * Prow[id.w] : 0.f) + base;
    f.x = p * g.x + q * pt.x;
    f.y = p * g.y + q * pt.y;
    f.z = p * g.z + q * pt.z;
    f.w = p * g.w + q * pt.w;

    out_final[i] = f;
    out_ptr[i]   = pt;
}

// ---------------------------------------------------------------------------
extern "C" void kernel_launch(void* const* d_in, const int* in_sizes, int n_in,
                              void* d_out, int out_size) {
    const int*   tok   = (const int*)  d_in[0];
    const float* tar   = (const float*)d_in[1];
    const float* gen   = (const float*)d_in[2];
    const float* enc   = (const float*)d_in[3];
    const float* dec   = (const float*)d_in[4];
    const float* heads = (const float*)d_in[5];
    const float* w     = (const float*)d_in[6];
    const float* wb    = (const float*)d_in[7];
    const float* psw   = (const float*)d_in[8];
    const float* psb   = (const float*)d_in[9];

    float* out       = (float*)d_out;
    float* out_final = out;
    float* out_ptr   = out + (long)BT * VV;
    float* out_pg    = out + 2L * BT * VV;

    k_reduce_heads<<<(BB * TT * II / 4 + 255) / 256, 256>>>((const float4*)heads);
    k_init_idx<<<(BB * VV + 255) / 256, 256>>>();
    k_slots<<<1, 32>>>(tok);
    k_ew<<<(BB * II + 7) / 8, 256>>>(enc, w);
    k_bt<<<BT, 256>>>(dec, tar, w, wb, out_pg);

    long total = (long)BT * V4;
    k_out<<<(int)((total + 255) / 256), 256>>>((const float4*)gen, psw, psb,
                                               (float4*)out_final, (float4*)out_ptr);
}

// round 3
// speedup vs baseline: 2.9535x; 2.9535x over previous
#include <cuda_runtime.h>

// Problem constants
#define BB 4
#define TT 256
#define II 512
#define HH 8
#define VV 32000
#define DD 512
#define BT (BB * TT)
#define V4 (VV / 4)

// Scratch (allocation-free rule: __device__ globals)
__device__ float g_attn[BB * TT * II];   // mean over heads  (2 MB)
__device__ int   g_idx[BB * VV];         // vocab -> slot or -1 (512 KB)
__device__ int   g_sl[BB * II];          // input pos -> slot
__device__ int   g_K[BB];                // distinct tokens per batch
__device__ float g_P[BB * TT * II];      // compact scattered sums (2 MB)
__device__ float g_lse[BT];
__device__ float g_pg[BT];
__device__ float g_ew[BB * II];          // enc row . w[0:D]

// ---------------------------------------------------------------------------
// 1) attn = mean_h attn_heads  (vectorized float4)
// ---------------------------------------------------------------------------
__global__ void k_reduce_heads(const float4* __restrict__ heads) {
    int i = blockIdx.x * blockDim.x + threadIdx.x;
    const int per_b = TT * II / 4;
    if (i >= BB * per_b) return;
    int b = i / per_b;
    int r = i - b * per_b;
    const float4* p = heads + (long)b * HH * per_b + r;
    float4 s = make_float4(0.f, 0.f, 0.f, 0.f);
#pragma unroll
    for (int h = 0; h < HH; h++) {
        float4 v = p[(long)h * per_b];
        s.x += v.x; s.y += v.y; s.z += v.z; s.w += v.w;
    }
    const float inv = 1.0f / HH;
    s.x *= inv; s.y *= inv; s.z *= inv; s.w *= inv;
    reinterpret_cast<float4*>(g_attn)[i] = s;
}

// ---------------------------------------------------------------------------
// 2a) idx = -1  and  K = 0
// ---------------------------------------------------------------------------
__global__ void k_init_idx() {
    int i = blockIdx.x * blockDim.x + threadIdx.x;
    if (i < BB * VV) g_idx[i] = -1;
    if (i < BB) g_K[i] = 0;
}

// 2b) fused slot assignment: one block, 1024 threads, 2 items each.
//     Phase A: owner claim via atomicMax (smallest position wins)
//     Phase B: owners take a compact slot id
//     Phase C: all positions look up their slot
__global__ void __launch_bounds__(1024) k_slots(const int* __restrict__ tok) {
    const int tid = threadIdx.x;
    int t0 = tok[tid], t1 = tok[tid + 1024];
    int b0 = tid / II, b1 = (tid + 1024) / II;
    int p0 = tid % II, p1 = (tid + 1024) % II;

    atomicMax(&g_idx[b0 * VV + t0], II - p0);
    atomicMax(&g_idx[b1 * VV + t1], II - p1);
    __syncthreads();

    if (g_idx[b0 * VV + t0] == II - p0) {
        int slot = atomicAdd(&g_K[b0], 1);
        g_idx[b0 * VV + t0] = slot;
    }
    if (g_idx[b1 * VV + t1] == II - p1) {
        int slot = atomicAdd(&g_K[b1], 1);
        g_idx[b1 * VV + t1] = slot;
    }
    __syncthreads();

    g_sl[tid]        = g_idx[b0 * VV + t0];
    g_sl[tid + 1024] = g_idx[b1 * VV + t1];
}

// ---------------------------------------------------------------------------
// 2c) ew[b,i] = enc[b,i,:] . w[0:D]   (one warp per row, w staged in smem)
// ---------------------------------------------------------------------------
__global__ void __launch_bounds__(256) k_ew(const float4* __restrict__ enc,
                                            const float4* __restrict__ w) {
    __shared__ float4 ws[DD / 4];                  // 128 float4 = 512 floats
    const int tid = threadIdx.x;
    if (tid < DD / 4) ws[tid] = w[tid];
    __syncthreads();

    int row  = blockIdx.x * 8 + (tid >> 5);        // 8 warps -> 8 rows
    int lane = tid & 31;
    if (row >= BB * II) return;
    const float4* e = enc + (long)row * (DD / 4);
    float s = 0.f;
#pragma unroll
    for (int q = 0; q < 4; q++) {
        float4 ev = e[lane + 32 * q];
        float4 wv = ws[lane + 32 * q];
        s += ev.x * wv.x + ev.y * wv.y + ev.z * wv.z + ev.w * wv.w;
    }
#pragma unroll
    for (int o = 16; o; o >>= 1) s += __shfl_down_sync(0xffffffffu, s, o);
    if (lane == 0) g_ew[row] = s;
}

// ---------------------------------------------------------------------------
// 3) Per-(b,t): compact scatter histogram, logsumexp, p_gen
// ---------------------------------------------------------------------------
__global__ void k_bt(const float* __restrict__ dec, const float* __restrict__ tar,
                     const float* __restrict__ w, const float* __restrict__ wb,
                     float* __restrict__ out_pg) {
    __shared__ float acc[II];
    __shared__ float r0[8], r1[8];
    const int bt  = blockIdx.x;
    const int b   = bt / TT;
    const int tid = threadIdx.x;

    acc[tid]       = 0.f;
    acc[tid + 256] = 0.f;
    __syncthreads();

    const float* arow = g_attn + (long)bt * II;
    float dot = 0.f;
    for (int i = tid; i < II; i += 256) {
        float a = arow[i];
        atomicAdd(&acc[g_sl[b * II + i]], a);
        dot += a * g_ew[b * II + i];
    }
    const float* drow = dec + (long)bt * DD;
    const float* trow = tar + (long)bt * DD;
    for (int d = tid; d < DD; d += 256)
        dot += drow[d] * w[DD + d] + trow[d] * w[2 * DD + d];
    __syncthreads();

    const int K = g_K[b];
    float se = 0.f;
    for (int k = tid; k < K; k += 256) se += expf(acc[k]);

    // dual block reduce (dot, se)
#pragma unroll
    for (int o = 16; o; o >>= 1) {
        dot += __shfl_down_sync(0xffffffffu, dot, o);
        se  += __shfl_down_sync(0xffffffffu, se, o);
    }
    int wp = tid >> 5, ln = tid & 31;
    if (ln == 0) { r0[wp] = dot; r1[wp] = se; }
    __syncthreads();
    if (tid == 0) {
        float dtot = 0.f, stot = 0.f;
#pragma unroll
        for (int q = 0; q < 8; q++) { dtot += r0[q]; stot += r1[q]; }
        float lse = logf((float)(VV - K) + stot);
        g_lse[bt] = lse;
        float p = 1.f / (1.f + expf(-(dtot + wb[0])));
        g_pg[bt]   = p;
        out_pg[bt] = p;
    }
    __syncthreads();
    float* Prow = g_P + (long)bt * II;
    Prow[tid]       = acc[tid];
    Prow[tid + 256] = acc[tid + 256];
}

// ---------------------------------------------------------------------------
// 4) Streaming output: final + pointer  (the HBM-bound kernel)
// ---------------------------------------------------------------------------
__global__ void __launch_bounds__(256) k_out(
    const float4* __restrict__ gen,
    const float*  __restrict__ psw_p, const float* __restrict__ psb_p,
    float4* __restrict__ out_final, float4* __restrict__ out_ptr)
{
    long i = (long)blockIdx.x * blockDim.x + threadIdx.x;
    const long total = (long)BT * V4;
    if (i >= total) return;
    int bt = (int)(i / V4);
    int v4 = (int)(i - (long)bt * V4);
    int b  = bt / TT;

    float4 g = __ldg(gen + i);
    const int4* idx4 = reinterpret_cast<const int4*>(g_idx);
    int4 id = __ldg(idx4 + (long)b * V4 + v4);

    float l   = __ldg(g_lse + bt);
    float p   = __ldg(g_pg + bt);
    float psw = __ldg(psw_p);
    float psb = __ldg(psb_p);
    float q    = 1.f - p;
    float base = psb - psw * l;   // pointer = psw*s + base
    const float* Prow = g_P + (long)bt * II;

    float4 pt, f;
    pt.x = (id.x >= 0 ? psw * Prow[id.x] : 0.f) + base;
    pt.y = (id.y >= 0 ? psw * Prow[id.y] : 0.f) + base;
    pt.z = (id.z >= 0 ? psw * Prow[id.z] : 0.f) + base;
    pt.w = (id.w >= 0 ? psw * Prow[id.w] : 0.f) + base;
    f.x = p * g.x + q * pt.x;
    f.y = p * g.y + q * pt.y;
    f.z = p * g.z + q * pt.z;
    f.w = p * g.w + q * pt.w;

    out_final[i] = f;
    out_ptr[i]   = pt;
}

// ---------------------------------------------------------------------------
extern "C" void kernel_launch(void* const* d_in, const int* in_sizes, int n_in,
                              void* d_out, int out_size) {
    const int*   tok   = (const int*)  d_in[0];
    const float* tar   = (const float*)d_in[1];
    const float* gen   = (const float*)d_in[2];
    const float* enc   = (const float*)d_in[3];
    const float* dec   = (const float*)d_in[4];
    const float* heads = (const float*)d_in[5];
    const float* w     = (const float*)d_in[6];
    const float* wb    = (const float*)d_in[7];
    const float* psw   = (const float*)d_in[8];
    const float* psb   = (const float*)d_in[9];

    float* out       = (float*)d_out;
    float* out_final = out;
    float* out_ptr   = out + (long)BT * VV;
    float* out_pg    = out + 2L * BT * VV;

    k_reduce_heads<<<(BB * TT * II / 4 + 255) / 256, 256>>>((const float4*)heads);
    k_init_idx<<<(BB * VV + 255) / 256, 256>>>();
    k_slots<<<1, 1024>>>(tok);
    k_ew<<<(BB * II + 7) / 8, 256>>>((const float4*)enc, (const float4*)w);
    k_bt<<<BT, 256>>>(dec, tar, w, wb, out_pg);

    long total = (long)BT * V4;
    k_out<<<(int)((total + 255) / 256), 256>>>((const float4*)gen, psw, psb,
                                               (float4*)out_final, (float4*)out_ptr);
}

// round 4
// speedup vs baseline: 3.1184x; 1.0558x over previous
#include <cuda_runtime.h>

// Problem constants
#define BB 4
#define TT 256
#define II 512
#define HH 8
#define VV 32000
#define DD 512
#define BT (BB * TT)
#define V4 (VV / 4)

// Scratch (allocation-free rule: __device__ globals)
__device__ int   g_idx[BB * VV];         // vocab -> slot or -1 (512 KB)
__device__ int   g_sl[BB * II];          // input pos -> slot
__device__ int   g_K[BB];                // distinct tokens per batch
__device__ float g_P[BB * TT * II];      // compact scattered sums (2 MB)
__device__ float g_lse[BT];
__device__ float g_pg[BT];
__device__ float g_ew[BB * II];          // enc row . w[0:D]

// ---------------------------------------------------------------------------
// 1) Fused prologue: blocks [0, IDX_BLKS) clear g_idx/g_K,
//    blocks [IDX_BLKS, IDX_BLKS+EW_BLKS) compute ew = enc . w[0:D]
// ---------------------------------------------------------------------------
#define IDX_BLKS ((BB * VV + 255) / 256)     // 500
#define EW_BLKS  ((BB * II) / 8)             // 256 (8 warps -> 8 rows per block)

__global__ void __launch_bounds__(256) k_pre(const float4* __restrict__ enc,
                                             const float4* __restrict__ w) {
    const int tid = threadIdx.x;
    if (blockIdx.x < IDX_BLKS) {
        int i = blockIdx.x * 256 + tid;
        if (i < BB * VV) g_idx[i] = -1;
        if (i < BB) g_K[i] = 0;
        return;
    }
    // ---- ew part ----
    __shared__ float4 ws[DD / 4];
    if (tid < DD / 4) ws[tid] = w[tid];
    __syncthreads();

    int row  = (blockIdx.x - IDX_BLKS) * 8 + (tid >> 5);
    int lane = tid & 31;
    const float4* e = enc + (long)row * (DD / 4);
    float s = 0.f;
#pragma unroll
    for (int q = 0; q < 4; q++) {
        float4 ev = e[lane + 32 * q];
        float4 wv = ws[lane + 32 * q];
        s += ev.x * wv.x + ev.y * wv.y + ev.z * wv.z + ev.w * wv.w;
    }
#pragma unroll
    for (int o = 16; o; o >>= 1) s += __shfl_down_sync(0xffffffffu, s, o);
    if (lane == 0) g_ew[row] = s;
}

// ---------------------------------------------------------------------------
// 2) fused slot assignment: one block, 1024 threads, 2 items each.
// ---------------------------------------------------------------------------
__global__ void __launch_bounds__(1024) k_slots(const int* __restrict__ tok) {
    const int tid = threadIdx.x;
    int t0 = tok[tid], t1 = tok[tid + 1024];
    int b0 = tid / II, b1 = (tid + 1024) / II;
    int p0 = tid % II, p1 = (tid + 1024) % II;

    atomicMax(&g_idx[b0 * VV + t0], II - p0);
    atomicMax(&g_idx[b1 * VV + t1], II - p1);
    __syncthreads();

    if (g_idx[b0 * VV + t0] == II - p0) {
        int slot = atomicAdd(&g_K[b0], 1);
        g_idx[b0 * VV + t0] = slot;
    }
    if (g_idx[b1 * VV + t1] == II - p1) {
        int slot = atomicAdd(&g_K[b1], 1);
        g_idx[b1 * VV + t1] = slot;
    }
    __syncthreads();

    g_sl[tid]        = g_idx[b0 * VV + t0];
    g_sl[tid + 1024] = g_idx[b1 * VV + t1];
}

// ---------------------------------------------------------------------------
// 3) Per-(b,t): inline head-mean, compact scatter histogram, logsumexp, p_gen
// ---------------------------------------------------------------------------
__global__ void __launch_bounds__(256) k_bt(
    const float* __restrict__ heads, const float* __restrict__ dec,
    const float* __restrict__ tar, const float* __restrict__ w,
    const float* __restrict__ wb, float* __restrict__ out_pg) {
    __shared__ float acc[II];
    __shared__ float r0[8], r1[8];
    const int bt  = blockIdx.x;
    const int b   = bt / TT;
    const int t   = bt % TT;
    const int tid = threadIdx.x;

    acc[tid]       = 0.f;
    acc[tid + 256] = 0.f;
    __syncthreads();

    // head base for (b, h=0, t, :)
    const float* hrow = heads + ((long)b * HH * TT + t) * II;
    const float inv = 1.0f / HH;
    float dot = 0.f;
#pragma unroll
    for (int rep = 0; rep < 2; rep++) {
        int i = tid + rep * 256;
        float a = 0.f;
#pragma unroll
        for (int h = 0; h < HH; h++)
            a += __ldg(hrow + (long)h * TT * II + i);
        a *= inv;
        atomicAdd(&acc[g_sl[b * II + i]], a);
        dot += a * g_ew[b * II + i];
    }
    const float* drow = dec + (long)bt * DD;
    const float* trow = tar + (long)bt * DD;
    for (int d = tid; d < DD; d += 256)
        dot += drow[d] * w[DD + d] + trow[d] * w[2 * DD + d];
    __syncthreads();

    const int K = g_K[b];
    float se = 0.f;
    for (int k = tid; k < K; k += 256) se += expf(acc[k]);

    // dual block reduce (dot, se)
#pragma unroll
    for (int o = 16; o; o >>= 1) {
        dot += __shfl_down_sync(0xffffffffu, dot, o);
        se  += __shfl_down_sync(0xffffffffu, se, o);
    }
    int wp = tid >> 5, ln = tid & 31;
    if (ln == 0) { r0[wp] = dot; r1[wp] = se; }
    __syncthreads();
    if (tid == 0) {
        float dtot = 0.f, stot = 0.f;
#pragma unroll
        for (int q = 0; q < 8; q++) { dtot += r0[q]; stot += r1[q]; }
        float lse = logf((float)(VV - K) + stot);
        g_lse[bt] = lse;
        float p = 1.f / (1.f + expf(-(dtot + wb[0])));
        g_pg[bt]   = p;
        out_pg[bt] = p;
    }
    __syncthreads();
    float* Prow = g_P + (long)bt * II;
    Prow[tid]       = acc[tid];
    Prow[tid + 256] = acc[tid + 256];
}

// ---------------------------------------------------------------------------
// 4) Streaming output: final + pointer  (the HBM-bound kernel)
//    gen streamed with .cs, outputs written with .wt (no L2 pollution);
//    L2 stays reserved for the reused g_idx / g_P gather tables.
// ---------------------------------------------------------------------------
__global__ void __launch_bounds__(256) k_out(
    const float4* __restrict__ gen,
    const float*  __restrict__ psw_p, const float* __restrict__ psb_p,
    float4* __restrict__ out_final, float4* __restrict__ out_ptr)
{
    long i = (long)blockIdx.x * blockDim.x + threadIdx.x;
    const long total = (long)BT * V4;
    if (i >= total) return;
    int bt = (int)(i / V4);
    int v4 = (int)(i - (long)bt * V4);
    int b  = bt / TT;

    float4 g = __ldcs(gen + i);
    const int4* idx4 = reinterpret_cast<const int4*>(g_idx);
    int4 id = __ldg(idx4 + (long)b * V4 + v4);

    float l   = __ldg(g_lse + bt);
    float p   = __ldg(g_pg + bt);
    float psw = __ldg(psw_p);
    float psb = __ldg(psb_p);
    float q    = 1.f - p;
    float base = psb - psw * l;   // pointer = psw*s + base
    const float* Prow = g_P + (long)bt * II;

    float4 pt, f;
    pt.x = (id.x >= 0 ? psw * Prow[id.x] : 0.f) + base;
    pt.y = (id.y >= 0 ? psw * Prow[id.y] : 0.f) + base;
    pt.z = (id.z >= 0 ? psw * Prow[id.z] : 0.f) + base;
    pt.w = (id.w >= 0 ? psw * Prow[id.w] : 0.f) + base;
    f.x = p * g.x + q * pt.x;
    f.y = p * g.y + q * pt.y;
    f.z = p * g.z + q * pt.z;
    f.w = p * g.w + q * pt.w;

    __stwt(out_final + i, f);
    __stwt(out_ptr + i, pt);
}

// ---------------------------------------------------------------------------
extern "C" void kernel_launch(void* const* d_in, const int* in_sizes, int n_in,
                              void* d_out, int out_size) {
    const int*   tok   = (const int*)  d_in[0];
    const float* tar   = (const float*)d_in[1];
    const float* gen   = (const float*)d_in[2];
    const float* enc   = (const float*)d_in[3];
    const float* dec   = (const float*)d_in[4];
    const float* heads = (const float*)d_in[5];
    const float* w     = (const float*)d_in[6];
    const float* wb    = (const float*)d_in[7];
    const float* psw   = (const float*)d_in[8];
    const float* psb   = (const float*)d_in[9];

    float* out       = (float*)d_out;
    float* out_final = out;
    float* out_ptr   = out + (long)BT * VV;
    float* out_pg    = out + 2L * BT * VV;

    k_pre<<<IDX_BLKS + EW_BLKS, 256>>>((const float4*)enc, (const float4*)w);
    k_slots<<<1, 1024>>>(tok);
    k_bt<<<BT, 256>>>(heads, dec, tar, w, wb, out_pg);

    long total = (long)BT * V4;
    k_out<<<(int)((total + 255) / 256), 256>>>((const float4*)gen, psw, psb,
                                               (float4*)out_final, (float4*)out_ptr);
}